// round 15
// baseline (speedup 1.0000x reference)
#include <cuda_runtime.h>
#include <cuda_fp16.h>
#include <cstdint>

#define D_MODEL 1024
#define SEQ     2048
#define BATCH   4
#define BS_TOT  8192
#define QK_PLANE ((size_t)BS_TOT * D_MODEL)

// ---------------- scratch (device globals; no allocations allowed) ----------
__device__ __align__(16) __half g_xs[(size_t)BS_TOT * D_MODEL];            // x fp16
__device__ __align__(16) __half g_wt[4][(size_t)D_MODEL * D_MODEL];        // W^T fp16 (q,k,v,o contiguous)
__device__ __align__(16) __half g_qkv[3 * (size_t)BS_TOT * D_MODEL];       // q|k|v planes (q pre-scaled 1/32; v natural [t][d])
__device__ __align__(16) float  g_bqkv[3 * D_MODEL];                       // bq|bk|bv concat
__device__ __align__(16) float  g_sc[(size_t)BATCH * SEQ * SEQ];           // scores fp32
__device__ __align__(16) __half g_ps[(size_t)BATCH * SEQ * SEQ];           // softmax fp16
__device__ __align__(16) __half g_as[(size_t)BS_TOT * D_MODEL];            // attn fp16

// ---------------- helpers ----------------
__device__ __forceinline__ uint32_t s2u(const void* p) {
    uint32_t a;
    asm("{ .reg .u64 t; cvta.to.shared.u64 t, %1; cvt.u32.u64 %0, t; }" : "=r"(a) : "l"(p));
    return a;
}

// 128B-row tile swizzle (8 x 16B chunks per row)
__device__ __forceinline__ uint32_t swz(int row, int chunk) {
    return (uint32_t)(row * 128 + ((chunk ^ (row & 7)) << 4));
}
// 256B-row tile swizzle (16 x 16B chunks per row); conflict-free for 8-row ldsm groups
__device__ __forceinline__ uint32_t swzB(int row, int chunk) {
    return (uint32_t)(row * 256 + ((chunk ^ (row & 7)) << 4));
}

__device__ __forceinline__ void ldsm4(uint32_t (&r)[4], uint32_t a) {
    asm volatile("ldmatrix.sync.aligned.m8n8.x4.shared.b16 {%0,%1,%2,%3}, [%4];"
                 : "=r"(r[0]), "=r"(r[1]), "=r"(r[2]), "=r"(r[3]) : "r"(a));
}
__device__ __forceinline__ void ldsm4t(uint32_t (&r)[4], uint32_t a) {
    asm volatile("ldmatrix.sync.aligned.m8n8.x4.trans.shared.b16 {%0,%1,%2,%3}, [%4];"
                 : "=r"(r[0]), "=r"(r[1]), "=r"(r[2]), "=r"(r[3]) : "r"(a));
}

__device__ __forceinline__ void mma16816(float (&d)[4], const uint32_t (&a)[4],
                                         uint32_t b0, uint32_t b1) {
    asm volatile(
        "mma.sync.aligned.m16n8k16.row.col.f32.f16.f16.f32 "
        "{%0,%1,%2,%3}, {%4,%5,%6,%7}, {%8,%9}, {%0,%1,%2,%3};"
        : "+f"(d[0]), "+f"(d[1]), "+f"(d[2]), "+f"(d[3])
        : "r"(a[0]), "r"(a[1]), "r"(a[2]), "r"(a[3]), "r"(b0), "r"(b1));
}

// ---------------- GEMM config (R9 proven) ------------------------------------
#define BM 128
#define BN 128
#define TILE_B  16384                // A/B tile: 16KB either geometry
#define STAGE_B (2 * TILE_B)
#define GEMM_SMEM (3 * STAGE_B)

#define OUT_F32   0
#define OUT_QKV   6   // fused q|k|v projection: seg = col>>10; q scaled 1/32; planes in Cg

// 128-row x 64-col (128B rows) tile loader
__device__ __forceinline__ void ld_tile(uint32_t sdst, const __half* src,
                                        size_t ld, int tid) {
#pragma unroll
    for (int j = 0; j < 4; j++) {
        int u = tid + 256 * j;
        int r = u >> 3, c = u & 7;
        uint32_t dst = sdst + swz(r, c);
        const void* s = src + (size_t)r * ld + c * 8;
        asm volatile("cp.async.cg.shared.global [%0], [%1], 16;" :: "r"(dst), "l"(s));
    }
}

// 64-row x 128-col (256B rows) natural-layout B tile loader
__device__ __forceinline__ void ld_tileN(uint32_t sdst, const __half* src,
                                         size_t ld, int tid) {
#pragma unroll
    for (int j = 0; j < 4; j++) {
        int u = tid + 256 * j;
        int r = u >> 4, c = u & 15;
        uint32_t dst = sdst + swzB(r, c);
        const void* s = src + (size_t)r * ld + c * 8;
        asm volatile("cp.async.cg.shared.global [%0], [%1], 16;" :: "r"(dst), "l"(s));
    }
}

// ---------------- GEMM (TN): D = A * B^T, B stored [N][K] --------------------
template<int MODE, bool HAS_BIAS>
__global__ __launch_bounds__(256, 2)
void gemm_mma(const __half* __restrict__ A,
              const __half* __restrict__ B,
              const float* __restrict__ bias,
              void* __restrict__ Cg,
              int N, int K, int ldb, float alpha,
              size_t sA, size_t sB, size_t sC)
{
    extern __shared__ __align__(128) char smem[];
    const uint32_t sb = s2u(smem);
    const int tid = threadIdx.x, lane = tid & 31, wid = tid >> 5;
    const int wm = wid & 1, wn = wid >> 1;
    const size_t lda = (size_t)K;

    A += blockIdx.z * sA + (size_t)blockIdx.y * BM * lda;
    B += blockIdx.z * sB + (size_t)blockIdx.x * BN * (size_t)ldb;

    float acc[4][4][4];
#pragma unroll
    for (int i = 0; i < 4; i++)
#pragma unroll
        for (int j = 0; j < 4; j++)
#pragma unroll
            for (int t = 0; t < 4; t++) acc[i][j][t] = 0.f;

    const int NC = K >> 6;

#pragma unroll
    for (int c = 0; c < 2; c++) {
        uint32_t st = sb + c * STAGE_B;
        ld_tile(st,          A + c * 64, lda, tid);
        ld_tile(st + TILE_B, B + c * 64, ldb, tid);
        asm volatile("cp.async.commit_group;" ::: "memory");
    }

    for (int i = 0; i < NC; i++) {
        asm volatile("cp.async.wait_group 1;" ::: "memory");
        __syncthreads();

        if (i + 2 < NC) {
            int c = i + 2;
            uint32_t st = sb + (c % 3) * STAGE_B;
            ld_tile(st,          A + c * 64, lda, tid);
            ld_tile(st + TILE_B, B + c * 64, ldb, tid);
        }
        asm volatile("cp.async.commit_group;" ::: "memory");

        uint32_t st = sb + (i % 3) * STAGE_B;
        uint32_t sA_ = st, sB_ = st + TILE_B;

#pragma unroll
        for (int ks = 0; ks < 4; ks++) {
            const int arow = lane & 15;
            const int achk = ks * 2 + (lane >> 4);

            uint32_t af[4][4], bf[2][4];
#pragma unroll
            for (int mt = 0; mt < 4; mt++)
                ldsm4(af[mt], sA_ + swz(wm * 64 + mt * 16 + arow, achk));
#pragma unroll
            for (int n2 = 0; n2 < 2; n2++)
                ldsm4(bf[n2], sB_ + swz(wn * 32 + n2 * 16 + arow, achk));

#pragma unroll
            for (int mt = 0; mt < 4; mt++)
#pragma unroll
                for (int nt = 0; nt < 4; nt++) {
                    const int n2 = nt >> 1, sub = nt & 1;
                    mma16816(acc[mt][nt], af[mt], bf[n2][sub], bf[n2][sub + 2]);
                }
        }
    }

    const int gm0 = blockIdx.y * BM + wm * 64;
    const int gn0 = blockIdx.x * BN + wn * 32;
    const int rq = lane >> 2, cq = (lane & 3) * 2;

    const int seg = (MODE == OUT_QKV) ? ((blockIdx.x * BN) >> 10) : 0;
    const float seg_alpha = (MODE == OUT_QKV) ? (seg ? 1.0f : 0.03125f) : alpha;

#pragma unroll
    for (int mt = 0; mt < 4; mt++)
#pragma unroll
        for (int nt = 0; nt < 4; nt++)
#pragma unroll
            for (int h = 0; h < 2; h++) {
                const int row = gm0 + mt * 16 + rq + h * 8;
                const int col = gn0 + nt * 8 + cq;
                float v0 = acc[mt][nt][h * 2 + 0];
                float v1 = acc[mt][nt][h * 2 + 1];
                if (HAS_BIAS) { v0 += __ldg(&bias[col]); v1 += __ldg(&bias[col + 1]); }
                if (MODE == OUT_QKV) {
                    v0 *= seg_alpha; v1 *= seg_alpha;
                    __half* C = (__half*)Cg + (size_t)seg * QK_PLANE
                              + (size_t)row * D_MODEL + (col & 1023);
                    *(__half2*)C = __halves2half2(__float2half_rn(v0), __float2half_rn(v1));
                } else {
                    v0 *= seg_alpha; v1 *= seg_alpha;
                    float* C = (float*)Cg + blockIdx.z * sC + (size_t)row * (size_t)N + col;
                    float2 v; v.x = v0; v.y = v1;
                    *(float2*)C = v;
                }
            }
}

// ---------------- GEMM (NN): D = A * B, B stored [K][N] natural --------------
// B fragments via ldmatrix.trans from 64x(128-col) tiles; half output, no bias.
__global__ __launch_bounds__(256, 2)
void gemm_nn(const __half* __restrict__ A,
             const __half* __restrict__ B,
             __half* __restrict__ Cg,
             int N, int K, int ldb,
             size_t sA, size_t sB, size_t sC)
{
    extern __shared__ __align__(128) char smem[];
    const uint32_t sb = s2u(smem);
    const int tid = threadIdx.x, lane = tid & 31, wid = tid >> 5;
    const int wm = wid & 1, wn = wid >> 1;
    const size_t lda = (size_t)K;

    A += blockIdx.z * sA + (size_t)blockIdx.y * BM * lda;
    B += blockIdx.z * sB + (size_t)blockIdx.x * BN;   // n offset within rows

    float acc[4][4][4];
#pragma unroll
    for (int i = 0; i < 4; i++)
#pragma unroll
        for (int j = 0; j < 4; j++)
#pragma unroll
            for (int t = 0; t < 4; t++) acc[i][j][t] = 0.f;

    const int NC = K >> 6;

#pragma unroll
    for (int c = 0; c < 2; c++) {
        uint32_t st = sb + c * STAGE_B;
        ld_tile (st,          A + c * 64,               lda, tid);
        ld_tileN(st + TILE_B, B + (size_t)(c * 64) * ldb, ldb, tid);
        asm volatile("cp.async.commit_group;" ::: "memory");
    }

    for (int i = 0; i < NC; i++) {
        asm volatile("cp.async.wait_group 1;" ::: "memory");
        __syncthreads();

        if (i + 2 < NC) {
            int c = i + 2;
            uint32_t st = sb + (c % 3) * STAGE_B;
            ld_tile (st,          A + c * 64,               lda, tid);
            ld_tileN(st + TILE_B, B + (size_t)(c * 64) * ldb, ldb, tid);
        }
        asm volatile("cp.async.commit_group;" ::: "memory");

        uint32_t st = sb + (i % 3) * STAGE_B;
        uint32_t sA_ = st, sB_ = st + TILE_B;

#pragma unroll
        for (int ks = 0; ks < 4; ks++) {
            const int arow = lane & 15;
            const int achk = ks * 2 + (lane >> 4);
            // trans-B lane mapping: k-row and n-chunk
            const int brow = ks * 16 + (lane & 7) + ((lane >> 4) << 3);
            const int bchk = (lane >> 3) & 1;

            uint32_t af[4][4], bf[2][4];
#pragma unroll
            for (int mt = 0; mt < 4; mt++)
                ldsm4(af[mt], sA_ + swz(wm * 64 + mt * 16 + arow, achk));
#pragma unroll
            for (int n2 = 0; n2 < 2; n2++)
                ldsm4t(bf[n2], sB_ + swzB(brow, wn * 4 + n2 * 2 + bchk));

#pragma unroll
            for (int mt = 0; mt < 4; mt++)
#pragma unroll
                for (int nt = 0; nt < 4; nt++) {
                    const int n2 = nt >> 1, sub = nt & 1;
                    mma16816(acc[mt][nt], af[mt], bf[n2][sub], bf[n2][sub + 2]);
                }
        }
    }

    const int gm0 = blockIdx.y * BM + wm * 64;
    const int gn0 = blockIdx.x * BN + wn * 32;
    const int rq = lane >> 2, cq = (lane & 3) * 2;

#pragma unroll
    for (int mt = 0; mt < 4; mt++)
#pragma unroll
        for (int nt = 0; nt < 4; nt++)
#pragma unroll
            for (int h = 0; h < 2; h++) {
                const int row = gm0 + mt * 16 + rq + h * 8;
                const int col = gn0 + nt * 8 + cq;
                __half* C = Cg + blockIdx.z * sC + (size_t)row * (size_t)N + col;
                *(__half2*)C = __halves2half2(__float2half_rn(acc[mt][nt][h * 2 + 0]),
                                              __float2half_rn(acc[mt][nt][h * 2 + 1]));
            }
}

// ---------------- conversion kernels ----------------------------------------
__global__ __launch_bounds__(256)
void cvt_h(const float* __restrict__ in, __half* __restrict__ out)
{
    size_t i = ((size_t)blockIdx.x * blockDim.x + threadIdx.x) * 4;
    float4 v = *(const float4*)(in + i);
    *(__half2*)(out + i)     = __halves2half2(__float2half_rn(v.x), __float2half_rn(v.y));
    *(__half2*)(out + i + 2) = __halves2half2(__float2half_rn(v.z), __float2half_rn(v.w));
}

__global__ void concat_bias3(const float* __restrict__ bq, const float* __restrict__ bk,
                             const float* __restrict__ bv, float* __restrict__ o)
{
    int i = blockIdx.x * blockDim.x + threadIdx.x;
    o[i]               = bq[i];
    o[i + D_MODEL]     = bk[i];
    o[i + 2 * D_MODEL] = bv[i];
}

struct W4 { const float* w[4]; };

__global__ void wtrans_h(W4 ws, __half* __restrict__ out)
{
    const float* in = ws.w[blockIdx.z];
    __half* o = out + (size_t)blockIdx.z * D_MODEL * D_MODEL;
    __shared__ float t[32][33];
    int r0 = blockIdx.y * 32, c0 = blockIdx.x * 32;
    t[threadIdx.y][threadIdx.x] = in[(size_t)(r0 + threadIdx.y) * D_MODEL + c0 + threadIdx.x];
    __syncthreads();
    float v = t[threadIdx.x][threadIdx.y];
    o[(size_t)(c0 + threadIdx.y) * D_MODEL + r0 + threadIdx.x] = __float2half_rn(v);
}

__global__ __launch_bounds__(256)
void softmax_h(const float* __restrict__ S, __half* __restrict__ P)
{
    const float* row = S + (size_t)blockIdx.x * SEQ;
    __half* prow = P + (size_t)blockIdx.x * SEQ;
    const int tid = threadIdx.x;

    float v[8];
    float m = -3.4e38f;
#pragma unroll
    for (int i = 0; i < 8; i++) { v[i] = row[tid + i * 256]; m = fmaxf(m, v[i]); }

    __shared__ float red[8];
#pragma unroll
    for (int o = 16; o > 0; o >>= 1) m = fmaxf(m, __shfl_xor_sync(0xffffffffu, m, o));
    if ((tid & 31) == 0) red[tid >> 5] = m;
    __syncthreads();
    m = red[0];
#pragma unroll
    for (int w = 1; w < 8; w++) m = fmaxf(m, red[w]);
    __syncthreads();

    float s = 0.f;
#pragma unroll
    for (int i = 0; i < 8; i++) { v[i] = __expf(v[i] - m); s += v[i]; }
#pragma unroll
    for (int o = 16; o > 0; o >>= 1) s += __shfl_xor_sync(0xffffffffu, s, o);
    if ((tid & 31) == 0) red[tid >> 5] = s;
    __syncthreads();
    s = 0.f;
#pragma unroll
    for (int w = 0; w < 8; w++) s += red[w];
    const float inv = 1.f / s;

#pragma unroll
    for (int i = 0; i < 8; i++)
        prow[tid + i * 256] = __float2half_rn(v[i] * inv);
}

// ---------------- host launcher ----------------------------------------------
extern "C" void kernel_launch(void* const* d_in, const int* in_sizes, int n_in,
                              void* d_out, int out_size)
{
    const float* x  = (const float*)d_in[0];
    const float* bq = (const float*)d_in[2];
    const float* bk = (const float*)d_in[4];
    const float* bv = (const float*)d_in[6];
    const float* bo = (const float*)d_in[8];
    float* out = (float*)d_out;

    __half *xs, *wt, *qkv, *ps, *as;
    float *sc, *bqkv;
    cudaGetSymbolAddress((void**)&xs,   g_xs);
    cudaGetSymbolAddress((void**)&wt,   g_wt);
    cudaGetSymbolAddress((void**)&qkv,  g_qkv);
    cudaGetSymbolAddress((void**)&bqkv, g_bqkv);
    cudaGetSymbolAddress((void**)&sc,   g_sc);
    cudaGetSymbolAddress((void**)&ps,   g_ps);
    cudaGetSymbolAddress((void**)&as,   g_as);
    const size_t WSTRIDE = (size_t)D_MODEL * D_MODEL;

    // one-time resource init (host-side only; no device allocations)
    static cudaStream_t s2 = nullptr;
    static cudaEvent_t e0 = nullptr, e_w = nullptr, e_s2d = nullptr;
    if (s2 == nullptr) {
        cudaStreamCreateWithFlags(&s2, cudaStreamNonBlocking);
        cudaEventCreateWithFlags(&e0,   cudaEventDisableTiming);
        cudaEventCreateWithFlags(&e_w,  cudaEventDisableTiming);
        cudaEventCreateWithFlags(&e_s2d, cudaEventDisableTiming);

        cudaFuncSetAttribute(gemm_mma<OUT_QKV, true>,  cudaFuncAttributeMaxDynamicSharedMemorySize, GEMM_SMEM);
        cudaFuncSetAttribute(gemm_mma<OUT_F32, false>, cudaFuncAttributeMaxDynamicSharedMemorySize, GEMM_SMEM);
        cudaFuncSetAttribute(gemm_mma<OUT_F32, true>,  cudaFuncAttributeMaxDynamicSharedMemorySize, GEMM_SMEM);
        cudaFuncSetAttribute(gemm_nn,                  cudaFuncAttributeMaxDynamicSharedMemorySize, GEMM_SMEM);
    }

    const size_t SC_B = (size_t)SEQ * SEQ;          // scores/probs per-batch stride
    const size_t QK_B = (size_t)SEQ * D_MODEL;      // per-batch row stride (q/k/v/attn)
    const size_t HALF_X = 2 * QK_B;                 // 4096 rows of 1024

    const dim3 gqkvH(3 * D_MODEL / BN, (BS_TOT / 2) / BM, 1);  // 24 x 32 = 768 CTAs
    const dim3 gsc2(SEQ / BN, SEQ / BM, 2);                    // 512 CTAs
    const dim3 gpv2(D_MODEL / BN, SEQ / BM, 2);                // 256 CTAs
    const dim3 gout2(D_MODEL / BN, (2 * SEQ) / BM, 1);         // 256 CTAs

    __half* vbase = qkv + 2 * QK_PLANE;             // v natural [t][d]

    // ---- fork ----
    cudaEventRecord(e0, 0);
    cudaStreamWaitEvent(s2, e0, 0);

    // default: x first half -> fp16
    cvt_h<<<(int)(HALF_X / 4 / 256), 256>>>(x, xs);

    // s2: x second half, weight transpose, bias concat
    cvt_h<<<(int)(HALF_X / 4 / 256), 256, 0, s2>>>(x + HALF_X, xs + HALF_X);
    W4 ws;
    ws.w[0] = (const float*)d_in[1]; ws.w[1] = (const float*)d_in[3];
    ws.w[2] = (const float*)d_in[5]; ws.w[3] = (const float*)d_in[7];
    wtrans_h<<<dim3(32, 32, 4), dim3(32, 32), 0, s2>>>(ws, wt);
    concat_bias3<<<D_MODEL / 256, 256, 0, s2>>>(bq, bk, bv, bqkv);
    cudaEventRecord(e_w, s2);

    // default chain A (batches 0,1): qkvA -> scores -> softmax -> pv -> out
    cudaStreamWaitEvent(0, e_w, 0);
    gemm_mma<OUT_QKV, true><<<gqkvH, 256, GEMM_SMEM>>>(
        xs, wt, bqkv, qkv, 3 * D_MODEL, D_MODEL, D_MODEL, 0.f, 0, 0, 0);

    gemm_mma<OUT_F32, false><<<gsc2, 256, GEMM_SMEM>>>(
        qkv, qkv + QK_PLANE, nullptr, sc,
        SEQ, D_MODEL, D_MODEL, 1.0f, QK_B, QK_B, SC_B);
    softmax_h<<<2 * SEQ, 256>>>(sc, ps);
    gemm_nn<<<gpv2, 256, GEMM_SMEM>>>(
        ps, vbase, as, D_MODEL, SEQ, D_MODEL, SC_B, QK_B, QK_B);
    gemm_mma<OUT_F32, true><<<gout2, 256, GEMM_SMEM>>>(
        as, wt + 3 * WSTRIDE, bo, out, D_MODEL, D_MODEL, D_MODEL, 1.0f, 0, 0, 0);

    // s2 chain B (batches 2,3): qkvB -> scores -> softmax -> pv -> out
    gemm_mma<OUT_QKV, true><<<gqkvH, 256, GEMM_SMEM, s2>>>(
        xs + HALF_X, wt, bqkv, qkv + HALF_X, 3 * D_MODEL, D_MODEL, D_MODEL, 0.f, 0, 0, 0);

    gemm_mma<OUT_F32, false><<<gsc2, 256, GEMM_SMEM, s2>>>(
        qkv + 2 * QK_B, qkv + QK_PLANE + 2 * QK_B, nullptr, sc + 2 * SC_B,
        SEQ, D_MODEL, D_MODEL, 1.0f, QK_B, QK_B, SC_B);
    softmax_h<<<2 * SEQ, 256, 0, s2>>>(sc + 2 * SC_B, ps + 2 * SC_B);
    gemm_nn<<<gpv2, 256, GEMM_SMEM, s2>>>(
        ps + 2 * SC_B, vbase + 2 * QK_B, as + 2 * QK_B,
        D_MODEL, SEQ, D_MODEL, SC_B, QK_B, QK_B);
    gemm_mma<OUT_F32, true><<<gout2, 256, GEMM_SMEM, s2>>>(
        as + 2 * QK_B, wt + 3 * WSTRIDE, bo, out + 2 * QK_B,
        D_MODEL, D_MODEL, D_MODEL, 1.0f, 0, 0, 0);

    // join s2 back into the origin stream
    cudaEventRecord(e_s2d, s2);
    cudaStreamWaitEvent(0, e_s2d, 0);
}

// round 16
// speedup vs baseline: 1.0072x; 1.0072x over previous
#include <cuda_runtime.h>
#include <cuda_fp16.h>
#include <cstdint>

#define D_MODEL 1024
#define SEQ     2048
#define BATCH   4
#define BS_TOT  8192
#define QK_PLANE ((size_t)BS_TOT * D_MODEL)

// ---------------- scratch (device globals; no allocations allowed) ----------
__device__ __align__(16) __half g_xs[(size_t)BS_TOT * D_MODEL];            // x fp16
__device__ __align__(16) __half g_wt[4][(size_t)D_MODEL * D_MODEL];        // W^T fp16 x4 (q,k contiguous)
__device__ __align__(16) __half g_qk[2 * (size_t)BS_TOT * D_MODEL];        // q|k planes (q pre-scaled 1/32)
__device__ __align__(16) float  g_bqk[2 * D_MODEL];                        // bq|bk concat
__device__ __align__(16) __half g_vts[(size_t)BATCH * D_MODEL * SEQ];      // v^T fp16 [b][1024][2048]
__device__ __align__(16) float  g_sc[(size_t)BATCH * SEQ * SEQ];           // scores fp32
__device__ __align__(16) __half g_ps[(size_t)BATCH * SEQ * SEQ];           // softmax fp16
__device__ __align__(16) __half g_as[(size_t)BS_TOT * D_MODEL];            // attn fp16

// ---------------- helpers ----------------
__device__ __forceinline__ uint32_t s2u(const void* p) {
    uint32_t a;
    asm("{ .reg .u64 t; cvta.to.shared.u64 t, %1; cvt.u32.u64 %0, t; }" : "=r"(a) : "l"(p));
    return a;
}

__device__ __forceinline__ uint32_t swz(int row, int chunk) {
    return (uint32_t)(row * 128 + ((chunk ^ (row & 7)) << 4));
}

__device__ __forceinline__ void ldsm4(uint32_t (&r)[4], uint32_t a) {
    asm volatile("ldmatrix.sync.aligned.m8n8.x4.shared.b16 {%0,%1,%2,%3}, [%4];"
                 : "=r"(r[0]), "=r"(r[1]), "=r"(r[2]), "=r"(r[3]) : "r"(a));
}

__device__ __forceinline__ void mma16816(float (&d)[4], const uint32_t (&a)[4],
                                         uint32_t b0, uint32_t b1) {
    asm volatile(
        "mma.sync.aligned.m16n8k16.row.col.f32.f16.f16.f32 "
        "{%0,%1,%2,%3}, {%4,%5,%6,%7}, {%8,%9}, {%0,%1,%2,%3};"
        : "+f"(d[0]), "+f"(d[1]), "+f"(d[2]), "+f"(d[3])
        : "r"(a[0]), "r"(a[1]), "r"(a[2]), "r"(a[3]), "r"(b0), "r"(b1));
}

// ---------------- plain fp16 GEMM: D = A * B^T (R9 proven config) -----------
#define BM 128
#define BN 128
#define TILE_B  16384
#define STAGE_B (2 * TILE_B)
#define GEMM_SMEM (3 * STAGE_B)

#define OUT_F32   0
#define OUT_HALF  2
#define OUT_VT    3
#define OUT_QK    5

__device__ __forceinline__ void ld_tile(uint32_t sdst, const __half* src,
                                        size_t ld, int tid) {
#pragma unroll
    for (int j = 0; j < 4; j++) {
        int u = tid + 256 * j;
        int r = u >> 3, c = u & 7;
        uint32_t dst = sdst + swz(r, c);
        const void* s = src + (size_t)r * ld + c * 8;
        asm volatile("cp.async.cg.shared.global [%0], [%1], 16;" :: "r"(dst), "l"(s));
    }
}

template<int MODE, bool HAS_BIAS>
__global__ __launch_bounds__(256, 2)
void gemm_mma(const __half* __restrict__ A,
              const __half* __restrict__ B,
              const float* __restrict__ bias,
              void* __restrict__ Cg,
              int N, int K, int ldb, float alpha,
              size_t sA, size_t sB, size_t sC)
{
    extern __shared__ __align__(128) char smem[];
    const uint32_t sb = s2u(smem);
    const int tid = threadIdx.x, lane = tid & 31, wid = tid >> 5;
    const int wm = wid & 1, wn = wid >> 1;
    const size_t lda = (size_t)K;

    A += blockIdx.z * sA + (size_t)blockIdx.y * BM * lda;
    B += blockIdx.z * sB + (size_t)blockIdx.x * BN * (size_t)ldb;

    float acc[4][4][4];
#pragma unroll
    for (int i = 0; i < 4; i++)
#pragma unroll
        for (int j = 0; j < 4; j++)
#pragma unroll
            for (int t = 0; t < 4; t++) acc[i][j][t] = 0.f;

    const int NC = K >> 6;

#pragma unroll
    for (int c = 0; c < 2; c++) {
        uint32_t st = sb + c * STAGE_B;
        ld_tile(st,          A + c * 64, lda, tid);
        ld_tile(st + TILE_B, B + c * 64, ldb, tid);
        asm volatile("cp.async.commit_group;" ::: "memory");
    }

    for (int i = 0; i < NC; i++) {
        asm volatile("cp.async.wait_group 1;" ::: "memory");
        __syncthreads();

        if (i + 2 < NC) {
            int c = i + 2;
            uint32_t st = sb + (c % 3) * STAGE_B;
            ld_tile(st,          A + c * 64, lda, tid);
            ld_tile(st + TILE_B, B + c * 64, ldb, tid);
        }
        asm volatile("cp.async.commit_group;" ::: "memory");

        uint32_t st = sb + (i % 3) * STAGE_B;
        uint32_t sA_ = st, sB_ = st + TILE_B;

#pragma unroll
        for (int ks = 0; ks < 4; ks++) {
            const int arow = lane & 15;
            const int achk = ks * 2 + (lane >> 4);

            uint32_t af[4][4], bf[2][4];
#pragma unroll
            for (int mt = 0; mt < 4; mt++)
                ldsm4(af[mt], sA_ + swz(wm * 64 + mt * 16 + arow, achk));
#pragma unroll
            for (int n2 = 0; n2 < 2; n2++)
                ldsm4(bf[n2], sB_ + swz(wn * 32 + n2 * 16 + arow, achk));

#pragma unroll
            for (int mt = 0; mt < 4; mt++)
#pragma unroll
                for (int nt = 0; nt < 4; nt++) {
                    const int n2 = nt >> 1, sub = nt & 1;
                    mma16816(acc[mt][nt], af[mt], bf[n2][sub], bf[n2][sub + 2]);
                }
        }
    }

    const int gm0 = blockIdx.y * BM + wm * 64;
    const int gn0 = blockIdx.x * BN + wn * 32;
    const int rq = lane >> 2, cq = (lane & 3) * 2;

    const int qk_seg = (MODE == OUT_QK) ? ((blockIdx.x * BN) >> 10) : 0;
    const float qk_alpha = (MODE == OUT_QK) ? (qk_seg ? 1.0f : 0.03125f) : 0.f;

#pragma unroll
    for (int mt = 0; mt < 4; mt++)
#pragma unroll
        for (int nt = 0; nt < 4; nt++)
#pragma unroll
            for (int h = 0; h < 2; h++) {
                const int row = gm0 + mt * 16 + rq + h * 8;
                const int col = gn0 + nt * 8 + cq;
                float v0 = acc[mt][nt][h * 2 + 0];
                float v1 = acc[mt][nt][h * 2 + 1];
                if (HAS_BIAS) {
                    if (MODE == OUT_VT) { float b = __ldg(&bias[row]); v0 += b; v1 += b; }
                    else { v0 += __ldg(&bias[col]); v1 += __ldg(&bias[col + 1]); }
                }
                if (MODE == OUT_QK) {
                    v0 *= qk_alpha; v1 *= qk_alpha;
                    __half* C = (__half*)Cg + (size_t)qk_seg * QK_PLANE
                              + (size_t)row * D_MODEL + (col & 1023);
                    *(__half2*)C = __halves2half2(__float2half_rn(v0), __float2half_rn(v1));
                } else if (MODE == OUT_HALF) {
                    v0 *= alpha; v1 *= alpha;
                    __half* C = (__half*)Cg + blockIdx.z * sC + (size_t)row * (size_t)N + col;
                    *(__half2*)C = __halves2half2(__float2half_rn(v0), __float2half_rn(v1));
                } else if (MODE == OUT_VT) {
                    const int b = col >> 11, t = col & 2047;
                    __half* C = (__half*)Cg + (size_t)b * D_MODEL * SEQ
                              + (size_t)row * SEQ + t;
                    *(__half2*)C = __halves2half2(__float2half_rn(v0), __float2half_rn(v1));
                } else {
                    float* C = (float*)Cg + blockIdx.z * sC + (size_t)row * (size_t)N + col;
                    float2 v; v.x = v0; v.y = v1;
                    *(float2*)C = v;
                }
            }
}

// ---------------- conversion kernels ----------------------------------------
__global__ __launch_bounds__(256)
void cvt_h(const float* __restrict__ in, __half* __restrict__ out)
{
    size_t i = ((size_t)blockIdx.x * blockDim.x + threadIdx.x) * 4;
    float4 v = *(const float4*)(in + i);
    *(__half2*)(out + i)     = __halves2half2(__float2half_rn(v.x), __float2half_rn(v.y));
    *(__half2*)(out + i + 2) = __halves2half2(__float2half_rn(v.z), __float2half_rn(v.w));
}

__global__ void concat_bias(const float* __restrict__ bq, const float* __restrict__ bk,
                            float* __restrict__ o)
{
    int i = blockIdx.x * blockDim.x + threadIdx.x;
    o[i]           = bq[i];
    o[i + D_MODEL] = bk[i];
}

struct W4 { const float* w[4]; };

__global__ void wtrans_h(W4 ws, __half* __restrict__ out)
{
    const float* in = ws.w[blockIdx.z];
    __half* o = out + (size_t)blockIdx.z * D_MODEL * D_MODEL;
    __shared__ float t[32][33];
    int r0 = blockIdx.y * 32, c0 = blockIdx.x * 32;
    t[threadIdx.y][threadIdx.x] = in[(size_t)(r0 + threadIdx.y) * D_MODEL + c0 + threadIdx.x];
    __syncthreads();
    float v = t[threadIdx.x][threadIdx.y];
    o[(size_t)(c0 + threadIdx.y) * D_MODEL + r0 + threadIdx.x] = __float2half_rn(v);
}

__global__ __launch_bounds__(256)
void softmax_h(const float* __restrict__ S, __half* __restrict__ P)
{
    const float* row = S + (size_t)blockIdx.x * SEQ;
    __half* prow = P + (size_t)blockIdx.x * SEQ;
    const int tid = threadIdx.x;

    float v[8];
    float m = -3.4e38f;
#pragma unroll
    for (int i = 0; i < 8; i++) { v[i] = row[tid + i * 256]; m = fmaxf(m, v[i]); }

    __shared__ float red[8];
#pragma unroll
    for (int o = 16; o > 0; o >>= 1) m = fmaxf(m, __shfl_xor_sync(0xffffffffu, m, o));
    if ((tid & 31) == 0) red[tid >> 5] = m;
    __syncthreads();
    m = red[0];
#pragma unroll
    for (int w = 1; w < 8; w++) m = fmaxf(m, red[w]);
    __syncthreads();

    float s = 0.f;
#pragma unroll
    for (int i = 0; i < 8; i++) { v[i] = __expf(v[i] - m); s += v[i]; }
#pragma unroll
    for (int o = 16; o > 0; o >>= 1) s += __shfl_xor_sync(0xffffffffu, s, o);
    if ((tid & 31) == 0) red[tid >> 5] = s;
    __syncthreads();
    s = 0.f;
#pragma unroll
    for (int w = 0; w < 8; w++) s += red[w];
    const float inv = 1.f / s;

#pragma unroll
    for (int i = 0; i < 8; i++)
        prow[tid + i * 256] = __float2half_rn(v[i] * inv);
}

// ---------------- host launcher ----------------------------------------------
extern "C" void kernel_launch(void* const* d_in, const int* in_sizes, int n_in,
                              void* d_out, int out_size)
{
    const float* x  = (const float*)d_in[0];
    const float* bq = (const float*)d_in[2];
    const float* bk = (const float*)d_in[4];
    const float* bv = (const float*)d_in[6];
    const float* bo = (const float*)d_in[8];
    float* out = (float*)d_out;

    __half *xs, *wt, *qk, *vts, *ps, *as;
    float *sc, *bqk;
    cudaGetSymbolAddress((void**)&xs,  g_xs);
    cudaGetSymbolAddress((void**)&wt,  g_wt);
    cudaGetSymbolAddress((void**)&qk,  g_qk);
    cudaGetSymbolAddress((void**)&bqk, g_bqk);
    cudaGetSymbolAddress((void**)&vts, g_vts);
    cudaGetSymbolAddress((void**)&sc,  g_sc);
    cudaGetSymbolAddress((void**)&ps,  g_ps);
    cudaGetSymbolAddress((void**)&as,  g_as);
    const size_t WSTRIDE = (size_t)D_MODEL * D_MODEL;

    // one-time resource init (host-side only; no device allocations)
    static cudaStream_t s2 = nullptr;
    static cudaEvent_t e0 = nullptr, e_xA = nullptr, e_xB = nullptr, e_w = nullptr,
                       e_vtA = nullptr, e_vtB = nullptr, e_s2d = nullptr;
    if (s2 == nullptr) {
        cudaStreamCreateWithFlags(&s2, cudaStreamNonBlocking);
        cudaEventCreateWithFlags(&e0,   cudaEventDisableTiming);
        cudaEventCreateWithFlags(&e_xA, cudaEventDisableTiming);
        cudaEventCreateWithFlags(&e_xB, cudaEventDisableTiming);
        cudaEventCreateWithFlags(&e_w,  cudaEventDisableTiming);
        cudaEventCreateWithFlags(&e_vtA, cudaEventDisableTiming);
        cudaEventCreateWithFlags(&e_vtB, cudaEventDisableTiming);
        cudaEventCreateWithFlags(&e_s2d, cudaEventDisableTiming);

        cudaFuncSetAttribute(gemm_mma<OUT_QK,   true>,  cudaFuncAttributeMaxDynamicSharedMemorySize, GEMM_SMEM);
        cudaFuncSetAttribute(gemm_mma<OUT_VT,   true>,  cudaFuncAttributeMaxDynamicSharedMemorySize, GEMM_SMEM);
        cudaFuncSetAttribute(gemm_mma<OUT_F32,  false>, cudaFuncAttributeMaxDynamicSharedMemorySize, GEMM_SMEM);
        cudaFuncSetAttribute(gemm_mma<OUT_HALF, false>, cudaFuncAttributeMaxDynamicSharedMemorySize, GEMM_SMEM);
        cudaFuncSetAttribute(gemm_mma<OUT_F32,  true>,  cudaFuncAttributeMaxDynamicSharedMemorySize, GEMM_SMEM);
    }

    const size_t SC_B = (size_t)SEQ * SEQ;          // scores/probs per-batch stride
    const size_t QK_B = (size_t)SEQ * D_MODEL;      // q/k per-batch row stride
    const size_t VT_B = (size_t)D_MODEL * SEQ;      // v^T per-batch stride
    const size_t AS_B = (size_t)SEQ * D_MODEL;      // attn rows per batch
    const size_t HALF_X = 2 * QK_B;                 // 4096 rows of 1024

    // half-grids
    const dim3 gqkH(2 * D_MODEL / BN, (BS_TOT / 2) / BM, 1);   // 16 x 32 = 512 CTAs
    const dim3 gvtH((BS_TOT / 2) / BN, D_MODEL / BM, 1);       // 32 x 8  = 256 CTAs
    const dim3 gsc2(SEQ / BN, SEQ / BM, 2);                    // 512 CTAs
    const dim3 gpv2(D_MODEL / BN, SEQ / BM, 2);                // 256 CTAs
    const dim3 gout2(D_MODEL / BN, (2 * SEQ) / BM, 1);         // 256 CTAs

    // ---- fork ----
    cudaEventRecord(e0, 0);
    cudaStreamWaitEvent(s2, e0, 0);

    // default: x first half -> fp16
    cvt_h<<<(int)(HALF_X / 4 / 256), 256>>>(x, xs);
    cudaEventRecord(e_xA, 0);

    // s2: x second half -> fp16, then weight transpose + bias concat
    cvt_h<<<(int)(HALF_X / 4 / 256), 256, 0, s2>>>(x + HALF_X, xs + HALF_X);
    cudaEventRecord(e_xB, s2);
    W4 ws;
    ws.w[0] = (const float*)d_in[1]; ws.w[1] = (const float*)d_in[3];
    ws.w[2] = (const float*)d_in[5]; ws.w[3] = (const float*)d_in[7];
    wtrans_h<<<dim3(32, 32, 4), dim3(32, 32), 0, s2>>>(ws, wt);
    concat_bias<<<D_MODEL / 256, 256, 0, s2>>>(bq, bk, bqk);
    cudaEventRecord(e_w, s2);

    // s2: vtA (batches 0,1) — needs wt (same stream) + xs first half (e_xA)
    cudaStreamWaitEvent(s2, e_xA, 0);
    gemm_mma<OUT_VT, true><<<gvtH, 256, GEMM_SMEM, s2>>>(
        wt + 2 * WSTRIDE, xs, bv, vts, BS_TOT / 2, D_MODEL, D_MODEL, 1.0f, 0, 0, 0);
    cudaEventRecord(e_vtA, s2);

    // default: vtB (batches 2,3) — needs wt (e_w) + xs second half (e_xB)
    cudaStreamWaitEvent(0, e_xB, 0);
    cudaStreamWaitEvent(0, e_w, 0);
    gemm_mma<OUT_VT, true><<<gvtH, 256, GEMM_SMEM>>>(
        wt + 2 * WSTRIDE, xs + HALF_X, bv, vts + 2 * VT_B,
        BS_TOT / 2, D_MODEL, D_MODEL, 1.0f, 0, 0, 0);
    cudaEventRecord(e_vtB, 0);

    // default: qkA (rows 0..4095) — xs first half (same stream), wt/bqk (e_w waited)
    gemm_mma<OUT_QK, true><<<gqkH, 256, GEMM_SMEM>>>(
        xs, wt, bqk, qk, 2 * D_MODEL, D_MODEL, D_MODEL, 0.f, 0, 0, 0);

    // s2: qkB (rows 4096..8191) — xs second half + wt/bqk all same-stream
    gemm_mma<OUT_QK, true><<<gqkH, 256, GEMM_SMEM, s2>>>(
        xs + HALF_X, wt, bqk, qk + HALF_X, 2 * D_MODEL, D_MODEL, D_MODEL, 0.f, 0, 0, 0);

    // chain A (b=0,1) on default — needs qkA (same stream) + vtA (s2)
    cudaStreamWaitEvent(0, e_vtA, 0);
    {
        const int b0 = 0;
        gemm_mma<OUT_F32, false><<<gsc2, 256, GEMM_SMEM>>>(
            qk + b0 * QK_B, qk + QK_PLANE + b0 * QK_B, nullptr, sc + b0 * SC_B,
            SEQ, D_MODEL, D_MODEL, 1.0f, QK_B, QK_B, SC_B);
        softmax_h<<<2 * SEQ, 256>>>(sc + b0 * SC_B, ps + b0 * SC_B);
        gemm_mma<OUT_HALF, false><<<gpv2, 256, GEMM_SMEM>>>(
            ps + b0 * SC_B, vts + b0 * VT_B, nullptr, as + b0 * AS_B,
            D_MODEL, SEQ, SEQ, 1.0f, SC_B, VT_B, AS_B);
        gemm_mma<OUT_F32, true><<<gout2, 256, GEMM_SMEM>>>(
            as + b0 * AS_B, wt + 3 * WSTRIDE, bo, out + b0 * AS_B,
            D_MODEL, D_MODEL, D_MODEL, 1.0f, 0, 0, 0);
    }

    // chain B (b=2,3) on s2 — needs qkB (same stream) + vtB (default)
    cudaStreamWaitEvent(s2, e_vtB, 0);
    {
        const int b0 = 2;
        gemm_mma<OUT_F32, false><<<gsc2, 256, GEMM_SMEM, s2>>>(
            qk + b0 * QK_B, qk + QK_PLANE + b0 * QK_B, nullptr, sc + b0 * SC_B,
            SEQ, D_MODEL, D_MODEL, 1.0f, QK_B, QK_B, SC_B);
        softmax_h<<<2 * SEQ, 256, 0, s2>>>(sc + b0 * SC_B, ps + b0 * SC_B);
        gemm_mma<OUT_HALF, false><<<gpv2, 256, GEMM_SMEM, s2>>>(
            ps + b0 * SC_B, vts + b0 * VT_B, nullptr, as + b0 * AS_B,
            D_MODEL, SEQ, SEQ, 1.0f, SC_B, VT_B, AS_B);
        gemm_mma<OUT_F32, true><<<gout2, 256, GEMM_SMEM, s2>>>(
            as + b0 * AS_B, wt + 3 * WSTRIDE, bo, out + b0 * AS_B,
            D_MODEL, D_MODEL, D_MODEL, 1.0f, 0, 0, 0);
    }

    // join s2 back into the origin stream
    cudaEventRecord(e_s2d, s2);
    cudaStreamWaitEvent(0, e_s2d, 0);
}

// round 17
// speedup vs baseline: 1.0200x; 1.0127x over previous
#include <cuda_runtime.h>
#include <cuda_fp16.h>
#include <cstdint>

#define D_MODEL 1024
#define SEQ     2048
#define BATCH   4
#define BS_TOT  8192
#define QK_PLANE ((size_t)BS_TOT * D_MODEL)

// ---------------- scratch (device globals; no allocations allowed) ----------
__device__ __align__(16) __half g_xs[(size_t)BS_TOT * D_MODEL];            // x fp16
__device__ __align__(16) __half g_wt[4][(size_t)D_MODEL * D_MODEL];        // W^T fp16 x4 (q,k contiguous)
__device__ __align__(16) __half g_qk[2 * (size_t)BS_TOT * D_MODEL];        // q|k planes (q pre-scaled 1/32)
__device__ __align__(16) float  g_bqk[2 * D_MODEL];                        // bq|bk concat
__device__ __align__(16) __half g_vts[(size_t)BATCH * D_MODEL * SEQ];      // v^T fp16 [b][1024][2048]
__device__ __align__(16) __half g_ps[(size_t)BATCH * SEQ * SEQ];           // scores fp16 -> softmax in-place
__device__ __align__(16) __half g_as[(size_t)BS_TOT * D_MODEL];            // attn fp16

// ---------------- helpers ----------------
__device__ __forceinline__ uint32_t s2u(const void* p) {
    uint32_t a;
    asm("{ .reg .u64 t; cvta.to.shared.u64 t, %1; cvt.u32.u64 %0, t; }" : "=r"(a) : "l"(p));
    return a;
}

__device__ __forceinline__ uint32_t swz(int row, int chunk) {
    return (uint32_t)(row * 128 + ((chunk ^ (row & 7)) << 4));
}

__device__ __forceinline__ void ldsm4(uint32_t (&r)[4], uint32_t a) {
    asm volatile("ldmatrix.sync.aligned.m8n8.x4.shared.b16 {%0,%1,%2,%3}, [%4];"
                 : "=r"(r[0]), "=r"(r[1]), "=r"(r[2]), "=r"(r[3]) : "r"(a));
}

__device__ __forceinline__ void mma16816(float (&d)[4], const uint32_t (&a)[4],
                                         uint32_t b0, uint32_t b1) {
    asm volatile(
        "mma.sync.aligned.m16n8k16.row.col.f32.f16.f16.f32 "
        "{%0,%1,%2,%3}, {%4,%5,%6,%7}, {%8,%9}, {%0,%1,%2,%3};"
        : "+f"(d[0]), "+f"(d[1]), "+f"(d[2]), "+f"(d[3])
        : "r"(a[0]), "r"(a[1]), "r"(a[2]), "r"(a[3]), "r"(b0), "r"(b1));
}

// ---------------- plain fp16 GEMM: D = A * B^T (R9 proven config) -----------
#define BM 128
#define BN 128
#define TILE_B  16384
#define STAGE_B (2 * TILE_B)
#define GEMM_SMEM (3 * STAGE_B)

#define OUT_F32   0
#define OUT_HALF  2
#define OUT_VT    3
#define OUT_QK    5

__device__ __forceinline__ void ld_tile(uint32_t sdst, const __half* src,
                                        size_t ld, int tid) {
#pragma unroll
    for (int j = 0; j < 4; j++) {
        int u = tid + 256 * j;
        int r = u >> 3, c = u & 7;
        uint32_t dst = sdst + swz(r, c);
        const void* s = src + (size_t)r * ld + c * 8;
        asm volatile("cp.async.cg.shared.global [%0], [%1], 16;" :: "r"(dst), "l"(s));
    }
}

template<int MODE, bool HAS_BIAS>
__global__ __launch_bounds__(256, 2)
void gemm_mma(const __half* __restrict__ A,
              const __half* __restrict__ B,
              const float* __restrict__ bias,
              void* __restrict__ Cg,
              int N, int K, int ldb, float alpha,
              size_t sA, size_t sB, size_t sC)
{
    extern __shared__ __align__(128) char smem[];
    const uint32_t sb = s2u(smem);
    const int tid = threadIdx.x, lane = tid & 31, wid = tid >> 5;
    const int wm = wid & 1, wn = wid >> 1;
    const size_t lda = (size_t)K;

    A += blockIdx.z * sA + (size_t)blockIdx.y * BM * lda;
    B += blockIdx.z * sB + (size_t)blockIdx.x * BN * (size_t)ldb;

    float acc[4][4][4];
#pragma unroll
    for (int i = 0; i < 4; i++)
#pragma unroll
        for (int j = 0; j < 4; j++)
#pragma unroll
            for (int t = 0; t < 4; t++) acc[i][j][t] = 0.f;

    const int NC = K >> 6;

#pragma unroll
    for (int c = 0; c < 2; c++) {
        uint32_t st = sb + c * STAGE_B;
        ld_tile(st,          A + c * 64, lda, tid);
        ld_tile(st + TILE_B, B + c * 64, ldb, tid);
        asm volatile("cp.async.commit_group;" ::: "memory");
    }

    for (int i = 0; i < NC; i++) {
        asm volatile("cp.async.wait_group 1;" ::: "memory");
        __syncthreads();

        if (i + 2 < NC) {
            int c = i + 2;
            uint32_t st = sb + (c % 3) * STAGE_B;
            ld_tile(st,          A + c * 64, lda, tid);
            ld_tile(st + TILE_B, B + c * 64, ldb, tid);
        }
        asm volatile("cp.async.commit_group;" ::: "memory");

        uint32_t st = sb + (i % 3) * STAGE_B;
        uint32_t sA_ = st, sB_ = st + TILE_B;

#pragma unroll
        for (int ks = 0; ks < 4; ks++) {
            const int arow = lane & 15;
            const int achk = ks * 2 + (lane >> 4);

            uint32_t af[4][4], bf[2][4];
#pragma unroll
            for (int mt = 0; mt < 4; mt++)
                ldsm4(af[mt], sA_ + swz(wm * 64 + mt * 16 + arow, achk));
#pragma unroll
            for (int n2 = 0; n2 < 2; n2++)
                ldsm4(bf[n2], sB_ + swz(wn * 32 + n2 * 16 + arow, achk));

#pragma unroll
            for (int mt = 0; mt < 4; mt++)
#pragma unroll
                for (int nt = 0; nt < 4; nt++) {
                    const int n2 = nt >> 1, sub = nt & 1;
                    mma16816(acc[mt][nt], af[mt], bf[n2][sub], bf[n2][sub + 2]);
                }
        }
    }

    const int gm0 = blockIdx.y * BM + wm * 64;
    const int gn0 = blockIdx.x * BN + wn * 32;
    const int rq = lane >> 2, cq = (lane & 3) * 2;

    const int qk_seg = (MODE == OUT_QK) ? ((blockIdx.x * BN) >> 10) : 0;
    const float qk_alpha = (MODE == OUT_QK) ? (qk_seg ? 1.0f : 0.03125f) : 0.f;

#pragma unroll
    for (int mt = 0; mt < 4; mt++)
#pragma unroll
        for (int nt = 0; nt < 4; nt++)
#pragma unroll
            for (int h = 0; h < 2; h++) {
                const int row = gm0 + mt * 16 + rq + h * 8;
                const int col = gn0 + nt * 8 + cq;
                float v0 = acc[mt][nt][h * 2 + 0];
                float v1 = acc[mt][nt][h * 2 + 1];
                if (HAS_BIAS) {
                    if (MODE == OUT_VT) { float b = __ldg(&bias[row]); v0 += b; v1 += b; }
                    else { v0 += __ldg(&bias[col]); v1 += __ldg(&bias[col + 1]); }
                }
                if (MODE == OUT_QK) {
                    v0 *= qk_alpha; v1 *= qk_alpha;
                    __half* C = (__half*)Cg + (size_t)qk_seg * QK_PLANE
                              + (size_t)row * D_MODEL + (col & 1023);
                    *(__half2*)C = __halves2half2(__float2half_rn(v0), __float2half_rn(v1));
                } else if (MODE == OUT_HALF) {
                    v0 *= alpha; v1 *= alpha;
                    __half* C = (__half*)Cg + blockIdx.z * sC + (size_t)row * (size_t)N + col;
                    *(__half2*)C = __halves2half2(__float2half_rn(v0), __float2half_rn(v1));
                } else if (MODE == OUT_VT) {
                    const int b = col >> 11, t = col & 2047;
                    __half* C = (__half*)Cg + (size_t)b * D_MODEL * SEQ
                              + (size_t)row * SEQ + t;
                    *(__half2*)C = __halves2half2(__float2half_rn(v0), __float2half_rn(v1));
                } else {
                    float* C = (float*)Cg + blockIdx.z * sC + (size_t)row * (size_t)N + col;
                    float2 v; v.x = v0; v.y = v1;
                    *(float2*)C = v;
                }
            }
}

// ---------------- conversion kernels ----------------------------------------
__global__ __launch_bounds__(256)
void cvt_h(const float* __restrict__ in, __half* __restrict__ out)
{
    size_t i = ((size_t)blockIdx.x * blockDim.x + threadIdx.x) * 4;
    float4 v = *(const float4*)(in + i);
    *(__half2*)(out + i)     = __halves2half2(__float2half_rn(v.x), __float2half_rn(v.y));
    *(__half2*)(out + i + 2) = __halves2half2(__float2half_rn(v.z), __float2half_rn(v.w));
}

__global__ void concat_bias(const float* __restrict__ bq, const float* __restrict__ bk,
                            float* __restrict__ o)
{
    int i = blockIdx.x * blockDim.x + threadIdx.x;
    o[i]           = bq[i];
    o[i + D_MODEL] = bk[i];
}

struct W4 { const float* w[4]; };

__global__ void wtrans_h(W4 ws, __half* __restrict__ out)
{
    const float* in = ws.w[blockIdx.z];
    __half* o = out + (size_t)blockIdx.z * D_MODEL * D_MODEL;
    __shared__ float t[32][33];
    int r0 = blockIdx.y * 32, c0 = blockIdx.x * 32;
    t[threadIdx.y][threadIdx.x] = in[(size_t)(r0 + threadIdx.y) * D_MODEL + c0 + threadIdx.x];
    __syncthreads();
    float v = t[threadIdx.x][threadIdx.y];
    o[(size_t)(c0 + threadIdx.y) * D_MODEL + r0 + threadIdx.x] = __float2half_rn(v);
}

// in-place softmax over fp16 rows
__global__ __launch_bounds__(256)
void softmax_hh(__half* __restrict__ S)
{
    __half* row = S + (size_t)blockIdx.x * SEQ;
    const int tid = threadIdx.x;

    float v[8];
    float m = -3.4e38f;
#pragma unroll
    for (int i = 0; i < 8; i++) {
        v[i] = __half2float(row[tid + i * 256]);
        m = fmaxf(m, v[i]);
    }

    __shared__ float red[8];
#pragma unroll
    for (int o = 16; o > 0; o >>= 1) m = fmaxf(m, __shfl_xor_sync(0xffffffffu, m, o));
    if ((tid & 31) == 0) red[tid >> 5] = m;
    __syncthreads();
    m = red[0];
#pragma unroll
    for (int w = 1; w < 8; w++) m = fmaxf(m, red[w]);
    __syncthreads();

    float s = 0.f;
#pragma unroll
    for (int i = 0; i < 8; i++) { v[i] = __expf(v[i] - m); s += v[i]; }
#pragma unroll
    for (int o = 16; o > 0; o >>= 1) s += __shfl_xor_sync(0xffffffffu, s, o);
    if ((tid & 31) == 0) red[tid >> 5] = s;
    __syncthreads();
    s = 0.f;
#pragma unroll
    for (int w = 0; w < 8; w++) s += red[w];
    const float inv = 1.f / s;

#pragma unroll
    for (int i = 0; i < 8; i++)
        row[tid + i * 256] = __float2half_rn(v[i] * inv);
}

// ---------------- host launcher ----------------------------------------------
extern "C" void kernel_launch(void* const* d_in, const int* in_sizes, int n_in,
                              void* d_out, int out_size)
{
    const float* x  = (const float*)d_in[0];
    const float* bq = (const float*)d_in[2];
    const float* bk = (const float*)d_in[4];
    const float* bv = (const float*)d_in[6];
    const float* bo = (const float*)d_in[8];
    float* out = (float*)d_out;

    __half *xs, *wt, *qk, *vts, *ps, *as;
    float *bqk;
    cudaGetSymbolAddress((void**)&xs,  g_xs);
    cudaGetSymbolAddress((void**)&wt,  g_wt);
    cudaGetSymbolAddress((void**)&qk,  g_qk);
    cudaGetSymbolAddress((void**)&bqk, g_bqk);
    cudaGetSymbolAddress((void**)&vts, g_vts);
    cudaGetSymbolAddress((void**)&ps,  g_ps);
    cudaGetSymbolAddress((void**)&as,  g_as);
    const size_t WSTRIDE = (size_t)D_MODEL * D_MODEL;

    // one-time resource init (host-side only; no device allocations)
    static cudaStream_t s2 = nullptr;
    static cudaEvent_t e0 = nullptr, e_xA = nullptr, e_xB = nullptr, e_w = nullptr,
                       e_vtA = nullptr, e_vtB = nullptr, e_s2d = nullptr;
    if (s2 == nullptr) {
        cudaStreamCreateWithFlags(&s2, cudaStreamNonBlocking);
        cudaEventCreateWithFlags(&e0,   cudaEventDisableTiming);
        cudaEventCreateWithFlags(&e_xA, cudaEventDisableTiming);
        cudaEventCreateWithFlags(&e_xB, cudaEventDisableTiming);
        cudaEventCreateWithFlags(&e_w,  cudaEventDisableTiming);
        cudaEventCreateWithFlags(&e_vtA, cudaEventDisableTiming);
        cudaEventCreateWithFlags(&e_vtB, cudaEventDisableTiming);
        cudaEventCreateWithFlags(&e_s2d, cudaEventDisableTiming);

        cudaFuncSetAttribute(gemm_mma<OUT_QK,   true>,  cudaFuncAttributeMaxDynamicSharedMemorySize, GEMM_SMEM);
        cudaFuncSetAttribute(gemm_mma<OUT_VT,   true>,  cudaFuncAttributeMaxDynamicSharedMemorySize, GEMM_SMEM);
        cudaFuncSetAttribute(gemm_mma<OUT_HALF, false>, cudaFuncAttributeMaxDynamicSharedMemorySize, GEMM_SMEM);
        cudaFuncSetAttribute(gemm_mma<OUT_F32,  true>,  cudaFuncAttributeMaxDynamicSharedMemorySize, GEMM_SMEM);
    }

    const size_t SC_B = (size_t)SEQ * SEQ;          // scores/probs per-batch stride
    const size_t QK_B = (size_t)SEQ * D_MODEL;      // q/k per-batch row stride
    const size_t VT_B = (size_t)D_MODEL * SEQ;      // v^T per-batch stride
    const size_t AS_B = (size_t)SEQ * D_MODEL;      // attn rows per batch
    const size_t HALF_X = 2 * QK_B;                 // 4096 rows of 1024

    // half-grids (R14 proven schedule)
    const dim3 gqkH(2 * D_MODEL / BN, (BS_TOT / 2) / BM, 1);   // 512 CTAs
    const dim3 gvtH((BS_TOT / 2) / BN, D_MODEL / BM, 1);       // 256 CTAs
    const dim3 gsc2(SEQ / BN, SEQ / BM, 2);                    // 512 CTAs
    const dim3 gpv2(D_MODEL / BN, SEQ / BM, 2);                // 256 CTAs
    const dim3 gout2(D_MODEL / BN, (2 * SEQ) / BM, 1);         // 256 CTAs

    // ---- fork ----
    cudaEventRecord(e0, 0);
    cudaStreamWaitEvent(s2, e0, 0);

    // default: x halves -> fp16
    cvt_h<<<(int)(HALF_X / 4 / 256), 256>>>(x, xs);
    cudaEventRecord(e_xA, 0);
    cvt_h<<<(int)(HALF_X / 4 / 256), 256>>>(x + HALF_X, xs + HALF_X);
    cudaEventRecord(e_xB, 0);

    // s2: weight transpose + bias concat
    W4 ws;
    ws.w[0] = (const float*)d_in[1]; ws.w[1] = (const float*)d_in[3];
    ws.w[2] = (const float*)d_in[5]; ws.w[3] = (const float*)d_in[7];
    wtrans_h<<<dim3(32, 32, 4), dim3(32, 32), 0, s2>>>(ws, wt);
    concat_bias<<<D_MODEL / 256, 256, 0, s2>>>(bq, bk, bqk);
    cudaEventRecord(e_w, s2);

    // s2: vtA (batches 0,1) after xs first half
    cudaStreamWaitEvent(s2, e_xA, 0);
    gemm_mma<OUT_VT, true><<<gvtH, 256, GEMM_SMEM, s2>>>(
        wt + 2 * WSTRIDE, xs, bv, vts, BS_TOT / 2, D_MODEL, D_MODEL, 1.0f, 0, 0, 0);
    cudaEventRecord(e_vtA, s2);

    // default: vtB (batches 2,3) — needs wt + xs second half (same stream)
    cudaStreamWaitEvent(0, e_w, 0);
    gemm_mma<OUT_VT, true><<<gvtH, 256, GEMM_SMEM>>>(
        wt + 2 * WSTRIDE, xs + HALF_X, bv, vts + 2 * VT_B,
        BS_TOT / 2, D_MODEL, D_MODEL, 1.0f, 0, 0, 0);
    cudaEventRecord(e_vtB, 0);

    // default: qkA (rows 0..4095)
    gemm_mma<OUT_QK, true><<<gqkH, 256, GEMM_SMEM>>>(
        xs, wt, bqk, qk, 2 * D_MODEL, D_MODEL, D_MODEL, 0.f, 0, 0, 0);

    // s2: qkB (rows 4096..8191) — needs xs second half
    cudaStreamWaitEvent(s2, e_xB, 0);
    gemm_mma<OUT_QK, true><<<gqkH, 256, GEMM_SMEM, s2>>>(
        xs + HALF_X, wt, bqk, qk + HALF_X, 2 * D_MODEL, D_MODEL, D_MODEL, 0.f, 0, 0, 0);

    // chain A (b=0,1) on default — needs qkA (same stream) + vtA (s2)
    cudaStreamWaitEvent(0, e_vtA, 0);
    {
        const int b0 = 0;
        // scores -> fp16 directly into ps
        gemm_mma<OUT_HALF, false><<<gsc2, 256, GEMM_SMEM>>>(
            qk + b0 * QK_B, qk + QK_PLANE + b0 * QK_B, nullptr, ps + b0 * SC_B,
            SEQ, D_MODEL, D_MODEL, 1.0f, QK_B, QK_B, SC_B);
        softmax_hh<<<2 * SEQ, 256>>>(ps + b0 * SC_B);
        gemm_mma<OUT_HALF, false><<<gpv2, 256, GEMM_SMEM>>>(
            ps + b0 * SC_B, vts + b0 * VT_B, nullptr, as + b0 * AS_B,
            D_MODEL, SEQ, SEQ, 1.0f, SC_B, VT_B, AS_B);
        gemm_mma<OUT_F32, true><<<gout2, 256, GEMM_SMEM>>>(
            as + b0 * AS_B, wt + 3 * WSTRIDE, bo, out + b0 * AS_B,
            D_MODEL, D_MODEL, D_MODEL, 1.0f, 0, 0, 0);
    }

    // chain B (b=2,3) on s2 — needs qkB (same stream) + vtB (default)
    cudaStreamWaitEvent(s2, e_vtB, 0);
    {
        const int b0 = 2;
        gemm_mma<OUT_HALF, false><<<gsc2, 256, GEMM_SMEM, s2>>>(
            qk + b0 * QK_B, qk + QK_PLANE + b0 * QK_B, nullptr, ps + b0 * SC_B,
            SEQ, D_MODEL, D_MODEL, 1.0f, QK_B, QK_B, SC_B);
        softmax_hh<<<2 * SEQ, 256, 0, s2>>>(ps + b0 * SC_B);
        gemm_mma<OUT_HALF, false><<<gpv2, 256, GEMM_SMEM, s2>>>(
            ps + b0 * SC_B, vts + b0 * VT_B, nullptr, as + b0 * AS_B,
            D_MODEL, SEQ, SEQ, 1.0f, SC_B, VT_B, AS_B);
        gemm_mma<OUT_F32, true><<<gout2, 256, GEMM_SMEM, s2>>>(
            as + b0 * AS_B, wt + 3 * WSTRIDE, bo, out + b0 * AS_B,
            D_MODEL, D_MODEL, D_MODEL, 1.0f, 0, 0, 0);
    }

    // join s2 back into the origin stream
    cudaEventRecord(e_s2d, s2);
    cudaStreamWaitEvent(0, e_s2d, 0);
}